// round 6
// baseline (speedup 1.0000x reference)
#include <cuda_runtime.h>
#include <cuda_bf16.h>
#include <cstdint>

constexpr int kB = 8, kN = 4096, kD = 1024, kNQ = 64;
constexpr int kTOPK = 1024;
constexpr int KC = 16;     // fp32 gemm K-chunk (qw)
constexpr int AP = 132;
constexpr int STG = KC * AP;
constexpr int kSPLIT = 16; // qw split-K

// ---- scores_mma smem geometry (bf16 units / bytes) ----
constexpr int ASTR = 40;                 // A tile row stride (b16), padded
constexpr int BSTR = 72;                 // B tile row stride (b16), padded
constexpr int A_SZ = 128 * ASTR;         // 5120 b16 per A term tile
constexpr int B_SZ = 32 * BSTR;          // 2304 b16 per B term tile
constexpr int STAGE_B16 = 2 * A_SZ + 2 * B_SZ;      // 14848
constexpr int STAGE_BYTES = STAGE_B16 * 2;          // 29696
constexpr int OFF_A2 = A_SZ * 2;                    // 10240 B
constexpr int OFF_B1 = 2 * A_SZ * 2;                // 20480 B
constexpr int OFF_B2 = OFF_B1 + B_SZ * 2;           // 25088 B
constexpr int SMEM_MMA = 2 * STAGE_BYTES;           // 59392 B

// ---------------- scratch ----------------
__device__ float g_QW[kNQ * kD];
__device__ float g_QWp[kSPLIT * kNQ * kD];
__device__ float g_qb[kNQ];
__device__ float g_bias[kB * kN];
__device__ __align__(16) unsigned short g_B1t[kD * kNQ];  // hi(QW)^T [k][q]
__device__ __align__(16) unsigned short g_B2t[kD * kNQ];  // lo(QW)^T [k][q]
__device__ float g_S[(size_t)kB * kNQ * kN];
__device__ float g_lse[kB * kNQ];
__device__ float g_logit[kB * kN];
__device__ int   g_idx[kB * kTOPK];

// ---------------- f32x2 helpers ----------------
__device__ __forceinline__ void f32x2_unpack(unsigned long long v, float& lo, float& hi) {
    asm("mov.b64 {%0, %1}, %2;" : "=f"(lo), "=f"(hi) : "l"(v));
}
__device__ __forceinline__ unsigned long long f32x2_fma(unsigned long long a,
                                                        unsigned long long b,
                                                        unsigned long long c) {
    unsigned long long d;
    asm("fma.rn.f32x2 %0, %1, %2, %3;" : "=l"(d) : "l"(a), "l"(b), "l"(c));
    return d;
}

// ---------------- warp-mma helpers (baseline PTX, no 'a' features) ----------------
__device__ __forceinline__ uint32_t s2u(const void* p) {
    uint32_t a;
    asm("{ .reg .u64 t; cvta.to.shared.u64 t, %1; cvt.u32.u64 %0, t; }" : "=r"(a) : "l"(p));
    return a;
}
__device__ __forceinline__ void ldsm4(uint32_t* r, uint32_t addr) {
    asm volatile("ldmatrix.sync.aligned.m8n8.x4.shared.b16 {%0,%1,%2,%3}, [%4];"
                 : "=r"(r[0]), "=r"(r[1]), "=r"(r[2]), "=r"(r[3]) : "r"(addr));
}
__device__ __forceinline__ void ldsm4t(uint32_t* r, uint32_t addr) {
    asm volatile("ldmatrix.sync.aligned.m8n8.x4.trans.shared.b16 {%0,%1,%2,%3}, [%4];"
                 : "=r"(r[0]), "=r"(r[1]), "=r"(r[2]), "=r"(r[3]) : "r"(addr));
}
__device__ __forceinline__ void mma_bf16(float* c, const uint32_t* a, uint32_t b0, uint32_t b1) {
    asm volatile("mma.sync.aligned.m16n8k16.row.col.f32.bf16.bf16.f32 "
                 "{%0,%1,%2,%3}, {%4,%5,%6,%7}, {%8,%9}, {%0,%1,%2,%3};"
                 : "+f"(c[0]), "+f"(c[1]), "+f"(c[2]), "+f"(c[3])
                 : "r"(a[0]), "r"(a[1]), "r"(a[2]), "r"(a[3]), "r"(b0), "r"(b1));
}
__device__ __forceinline__ uint32_t pack_bf16x2(__nv_bfloat16 lo, __nv_bfloat16 hi) {
    return (uint32_t)__bfloat16_as_ushort(lo) | ((uint32_t)__bfloat16_as_ushort(hi) << 16);
}

// ---------------- fp32 tile GEMM (qw only) ----------------
__device__ __forceinline__ void ldg_stage(const float* __restrict__ A,
                                          const float* __restrict__ Bm,
                                          int k0, float4 pa[2], float4& pb, int tid)
{
#pragma unroll
    for (int i = 0; i < 2; i++) {
        int idx = tid + i * 256;
        int r = idx >> 2, c4 = idx & 3;
        pa[i] = *(const float4*)(A + (size_t)r * kD + k0 + c4 * 4);
    }
    {
        int q = tid >> 2, c4 = tid & 3;
        pb = *(const float4*)(Bm + (size_t)q * kD + k0 + c4 * 4);
    }
}
__device__ __forceinline__ void sts_stage(float* As, float* Bs,
                                          const float4 pa[2], const float4& pb, int tid)
{
#pragma unroll
    for (int i = 0; i < 2; i++) {
        int idx = tid + i * 256;
        int r = idx >> 2, c4 = idx & 3;
        float* p = As + (c4 * 4) * AP + r;
        p[0] = pa[i].x; p[AP] = pa[i].y; p[2 * AP] = pa[i].z; p[3 * AP] = pa[i].w;
    }
    {
        int q = tid >> 2, c4 = tid & 3;
        float* p = Bs + (c4 * 4) * AP + 2 * q;
        p[0] = pb.x;      p[1] = pb.x;
        p[AP] = pb.y;     p[AP + 1] = pb.y;
        p[2 * AP] = pb.z; p[2 * AP + 1] = pb.z;
        p[3 * AP] = pb.w; p[3 * AP + 1] = pb.w;
    }
}
__device__ __forceinline__ void gemm128x64(const float* __restrict__ A,
                                           const float* __restrict__ Bm,
                                           int kbeg, int kend,
                                           float* As, float* Bs,
                                           unsigned long long c2[2][8])
{
    const int tid = threadIdx.x;
    const int w = tid >> 5, l = tid & 31;
#pragma unroll
    for (int p = 0; p < 2; p++)
#pragma unroll
        for (int c = 0; c < 8; c++) c2[p][c] = 0ull;

    float4 pa[2]; float4 pb;
    ldg_stage(A, Bm, kbeg, pa, pb, tid);
    sts_stage(As, Bs, pa, pb, tid);
    __syncthreads();

    const int ns = (kend - kbeg) >> 4;
    for (int s = 0; s < ns; s++) {
        const float* Ac = As + (s & 1) * STG;
        const float* Bc = Bs + (s & 1) * STG;
        if (s + 1 < ns) ldg_stage(A, Bm, kbeg + (s + 1) * KC, pa, pb, tid);
#pragma unroll
        for (int k = 0; k < KC; k++) {
            ulonglong2 a = *(const ulonglong2*)(Ac + k * AP + 4 * l);
            const float* bp = Bc + k * AP + 16 * w;
            ulonglong2 b0 = *(const ulonglong2*)(bp);
            ulonglong2 b1 = *(const ulonglong2*)(bp + 4);
            ulonglong2 b2 = *(const ulonglong2*)(bp + 8);
            ulonglong2 b3 = *(const ulonglong2*)(bp + 12);
            c2[0][0] = f32x2_fma(a.x, b0.x, c2[0][0]);
            c2[0][1] = f32x2_fma(a.x, b0.y, c2[0][1]);
            c2[0][2] = f32x2_fma(a.x, b1.x, c2[0][2]);
            c2[0][3] = f32x2_fma(a.x, b1.y, c2[0][3]);
            c2[0][4] = f32x2_fma(a.x, b2.x, c2[0][4]);
            c2[0][5] = f32x2_fma(a.x, b2.y, c2[0][5]);
            c2[0][6] = f32x2_fma(a.x, b3.x, c2[0][6]);
            c2[0][7] = f32x2_fma(a.x, b3.y, c2[0][7]);
            c2[1][0] = f32x2_fma(a.y, b0.x, c2[1][0]);
            c2[1][1] = f32x2_fma(a.y, b0.y, c2[1][1]);
            c2[1][2] = f32x2_fma(a.y, b1.x, c2[1][2]);
            c2[1][3] = f32x2_fma(a.y, b1.y, c2[1][3]);
            c2[1][4] = f32x2_fma(a.y, b2.x, c2[1][4]);
            c2[1][5] = f32x2_fma(a.y, b2.y, c2[1][5]);
            c2[1][6] = f32x2_fma(a.y, b3.x, c2[1][6]);
            c2[1][7] = f32x2_fma(a.y, b3.y, c2[1][7]);
        }
        if (s + 1 < ns) {
            sts_stage(As + ((s + 1) & 1) * STG, Bs + ((s + 1) & 1) * STG, pa, pb, tid);
            __syncthreads();
        }
    }
}

// ---------------- 1) QW split-K partials ----------------
__global__ void __launch_bounds__(256, 2) qw_kernel(const float* __restrict__ kw,
                                                    const float* __restrict__ qe)
{
    __shared__ float As[2 * STG];
    __shared__ float Bs[2 * STG];
    const int d0 = blockIdx.x * 128;
    const int kc = blockIdx.y;
    unsigned long long c2[2][8];
    gemm128x64(kw + (size_t)d0 * kD, qe, kc * 64, kc * 64 + 64, As, Bs, c2);

    const int tid = threadIdx.x, w = tid >> 5, l = tid & 31;
    const int dbase = d0 + 4 * l;
    float* gp = g_QWp + (size_t)kc * (kNQ * kD);
#pragma unroll
    for (int c = 0; c < 8; c++) {
        const int q = 8 * w + c;
        float4 o;
        f32x2_unpack(c2[0][c], o.x, o.y);
        f32x2_unpack(c2[1][c], o.z, o.w);
        *(float4*)(gp + (size_t)q * kD + dbase) = o;
    }
}

// ---------------- 1b) reduce partials, scale 1/32 ----------------
__global__ void __launch_bounds__(256) qwred_kernel()
{
    const int i4 = blockIdx.x * 256 + threadIdx.x;
    float4 acc = make_float4(0.f, 0.f, 0.f, 0.f);
#pragma unroll
    for (int c = 0; c < kSPLIT; c++) {
        float4 v = ((const float4*)g_QWp)[(size_t)c * 16384 + i4];
        acc.x += v.x; acc.y += v.y; acc.z += v.z; acc.w += v.w;
    }
    acc.x *= 0.03125f; acc.y *= 0.03125f; acc.z *= 0.03125f; acc.w *= 0.03125f;
    ((float4*)g_QW)[i4] = acc;
}

// ---------------- 2) qb ----------------
__global__ void qb_kernel(const float* __restrict__ qe, const float* __restrict__ kb)
{
    const int q = threadIdx.x;
    const float* row = qe + (size_t)q * kD;
    float s0 = 0.f, s1 = 0.f, s2 = 0.f, s3 = 0.f;
    for (int h = 0; h < kD; h += 4) {
        s0 = fmaf(row[h + 0], kb[h + 0], s0);
        s1 = fmaf(row[h + 1], kb[h + 1], s1);
        s2 = fmaf(row[h + 2], kb[h + 2], s2);
        s3 = fmaf(row[h + 3], kb[h + 3], s3);
    }
    g_qb[q] = ((s0 + s1) + (s2 + s3)) * 0.03125f;
}

// ---------------- 2b) hi/lo bf16 split of QW, transposed to [k][q] ----------------
__global__ void __launch_bounds__(256) prepb_kernel()
{
    const int gid = blockIdx.x * 256 + threadIdx.x;   // 65536
    const int k = gid >> 6, q = gid & 63;
    float x = g_QW[q * kD + k];
    __nv_bfloat16 h1 = __float2bfloat16(x);
    __nv_bfloat16 h2 = __float2bfloat16(x - __bfloat162float(h1));
    g_B1t[k * kNQ + q] = __bfloat16_as_ushort(h1);
    g_B2t[k * kNQ + q] = __bfloat16_as_ushort(h2);
}

// ---------------- 3) density bias: 4 threads per token ----------------
__global__ void __launch_bounds__(256) density_kernel(
    const float* __restrict__ dens, const float* __restrict__ w1,
    const float* __restrict__ b1, const float* __restrict__ w2,
    const float* __restrict__ b2)
{
    __shared__ float4 sw1[512], sb1[512], sw2[512];
    const int tid = threadIdx.x;
    for (int i = tid; i < 512; i += 256) {
        sw1[i] = ((const float4*)w1)[i];
        sb1[i] = ((const float4*)b1)[i];
        sw2[i] = ((const float4*)w2)[i];
    }
    __syncthreads();
    const int t = blockIdx.x * 64 + (tid >> 2);
    const int sub = tid & 3;
    const float d = dens[t];
    float a0 = 0.f, a1 = 0.f, a2 = 0.f, a3 = 0.f;
    const int j0 = sub * 128;
#pragma unroll 4
    for (int j = j0; j < j0 + 128; j++) {
        float4 w = sw1[j], bb = sb1[j], v = sw2[j];
        float h0 = fmaxf(fmaf(d, w.x, bb.x), 0.f);
        float h1 = fmaxf(fmaf(d, w.y, bb.y), 0.f);
        float h2 = fmaxf(fmaf(d, w.z, bb.z), 0.f);
        float h3 = fmaxf(fmaf(d, w.w, bb.w), 0.f);
        a0 = fmaf(h0, v.x, a0);
        a1 = fmaf(h1, v.y, a1);
        a2 = fmaf(h2, v.z, a2);
        a3 = fmaf(h3, v.w, a3);
    }
    float v = (a0 + a1) + (a2 + a3);
    v += __shfl_xor_sync(0xffffffffu, v, 1);
    v += __shfl_xor_sync(0xffffffffu, v, 2);
    if (sub == 0) g_bias[t] = v + b2[0];
}

// ---------------- 4) scores via warp-mma bf16 (3-term split) ----------------
__global__ void __launch_bounds__(256, 2) scores_mma(const float* __restrict__ tf)
{
    extern __shared__ __align__(16) unsigned short sm[];
    const int tid = threadIdx.x, w = tid >> 5, lane = tid & 31;
    const int b = blockIdx.y, n0 = blockIdx.x * 128;
    const uint32_t sbase = s2u(sm);

    const float* Abase = tf + ((size_t)(b * kN + n0)) * kD;
    const int arow = tid >> 1, ahalf = tid & 1;           // 16 floats each
    const int brow = tid >> 3, bseg = tid & 7;            // 8 b16 each per term

    float4 pa[4]; uint4 pb1, pb2;

    auto LDG = [&](int c) {
        const float* p = Abase + (size_t)arow * kD + c * 32 + ahalf * 16;
#pragma unroll
        for (int i = 0; i < 4; i++) pa[i] = *(const float4*)(p + i * 4);
        pb1 = *(const uint4*)(g_B1t + (size_t)(c * 32 + brow) * kNQ + bseg * 8);
        pb2 = *(const uint4*)(g_B2t + (size_t)(c * 32 + brow) * kNQ + bseg * 8);
    };
    auto STS = [&](int st) {
        unsigned short* S = sm + st * STAGE_B16;
        uint32_t* A1u = (uint32_t*)S;
        uint32_t* A2u = A1u + A_SZ / 2;
        const float xs[16] = {pa[0].x, pa[0].y, pa[0].z, pa[0].w,
                              pa[1].x, pa[1].y, pa[1].z, pa[1].w,
                              pa[2].x, pa[2].y, pa[2].z, pa[2].w,
                              pa[3].x, pa[3].y, pa[3].z, pa[3].w};
        const int ub = arow * (ASTR / 2) + ahalf * 8;
#pragma unroll
        for (int j = 0; j < 8; j++) {
            float x0 = xs[2 * j], x1 = xs[2 * j + 1];
            __nv_bfloat16 h0 = __float2bfloat16(x0);
            __nv_bfloat16 h1 = __float2bfloat16(x1);
            __nv_bfloat16 l0 = __float2bfloat16(x0 - __bfloat162float(h0));
            __nv_bfloat16 l1 = __float2bfloat16(x1 - __bfloat162float(h1));
            A1u[ub + j] = pack_bf16x2(h0, h1);
            A2u[ub + j] = pack_bf16x2(l0, l1);
        }
        char* Sb = (char*)S;
        *(uint4*)(Sb + OFF_B1 + brow * (BSTR * 2) + bseg * 16) = pb1;
        *(uint4*)(Sb + OFF_B2 + brow * (BSTR * 2) + bseg * 16) = pb2;
    };

    float acc[8][4];
#pragma unroll
    for (int n = 0; n < 8; n++)
#pragma unroll
        for (int i = 0; i < 4; i++) acc[n][i] = 0.f;

    LDG(0);
    STS(0);
    __syncthreads();

    const uint32_t a_lane_off = ((16 * w + (lane & 15)) * ASTR + (lane >> 4) * 8) * 2;
    const uint32_t b_lane_row = (lane & 7);
    const uint32_t b_lane_n = (lane >> 3) * 8;

    for (int c = 0; c < 32; c++) {
        if (c + 1 < 32) LDG(c + 1);
        const uint32_t sA = sbase + (c & 1) * STAGE_BYTES;
#pragma unroll
        for (int s = 0; s < 2; s++) {
            uint32_t A1f[4], A2f[4];
            ldsm4(A1f, sA + a_lane_off + s * 32);
            ldsm4(A2f, sA + OFF_A2 + a_lane_off + s * 32);
            // term B1: A1*B1 and A2*B1
            {
                uint32_t Bf[8][2];
#pragma unroll
                for (int nh = 0; nh < 2; nh++)
#pragma unroll
                    for (int ko = 0; ko < 2; ko++) {
                        uint32_t r[4];
                        ldsm4t(r, sA + OFF_B1 +
                                   ((s * 16 + ko * 8 + b_lane_row) * BSTR +
                                    (nh * 4) * 8 + b_lane_n) * 2);
#pragma unroll
                        for (int g = 0; g < 4; g++) Bf[nh * 4 + g][ko] = r[g];
                    }
#pragma unroll
                for (int n = 0; n < 8; n++) {
                    mma_bf16(acc[n], A1f, Bf[n][0], Bf[n][1]);
                    mma_bf16(acc[n], A2f, Bf[n][0], Bf[n][1]);
                }
            }
            // term B2: A1*B2
            {
                uint32_t Bf[8][2];
#pragma unroll
                for (int nh = 0; nh < 2; nh++)
#pragma unroll
                    for (int ko = 0; ko < 2; ko++) {
                        uint32_t r[4];
                        ldsm4t(r, sA + OFF_B2 +
                                   ((s * 16 + ko * 8 + b_lane_row) * BSTR +
                                    (nh * 4) * 8 + b_lane_n) * 2);
#pragma unroll
                        for (int g = 0; g < 4; g++) Bf[nh * 4 + g][ko] = r[g];
                    }
#pragma unroll
                for (int n = 0; n < 8; n++)
                    mma_bf16(acc[n], A1f, Bf[n][0], Bf[n][1]);
            }
        }
        if (c + 1 < 32) {
            STS((c + 1) & 1);
        }
        __syncthreads();
    }

    // ---- epilogue: transpose through smem, coalesced store ----
    float* Cs = (float*)sm;                 // [64][132]
    const int r0 = 16 * w + (lane >> 2);
    const int q0 = 2 * (lane & 3);
#pragma unroll
    for (int nt = 0; nt < 8; nt++) {
        const int q = nt * 8 + q0;
        Cs[(q + 0) * 132 + r0]     = acc[nt][0];
        Cs[(q + 1) * 132 + r0]     = acc[nt][1];
        Cs[(q + 0) * 132 + r0 + 8] = acc[nt][2];
        Cs[(q + 1) * 132 + r0 + 8] = acc[nt][3];
    }
    __syncthreads();
    const int q = tid >> 2, seg = tid & 3;
    const float addq = g_qb[q];
    float* outp = g_S + ((size_t)(b * kNQ + q)) * kN + n0 + seg * 32;
    const float* biasp = g_bias + b * kN + n0 + seg * 32;
    const float* cp = Cs + q * 132 + seg * 32;
#pragma unroll
    for (int j = 0; j < 8; j++) {
        float4 v = *(const float4*)(cp + j * 4);
        float4 bb = *(const float4*)(biasp + j * 4);
        v.x += addq + bb.x; v.y += addq + bb.y;
        v.z += addq + bb.z; v.w += addq + bb.w;
        *(float4*)(outp + j * 4) = v;
    }
}

// ---------------- 5) logsumexp ----------------
__global__ void __launch_bounds__(256) lse_kernel()
{
    const int row = blockIdx.x;
    const float4* s4 = (const float4*)(g_S + (size_t)row * kN);
    const int tid = threadIdx.x;
    __shared__ float red[8];

    float m = -3.402823466e38f;
    for (int i = tid; i < kN / 4; i += 256) {
        float4 v = s4[i];
        m = fmaxf(m, fmaxf(fmaxf(v.x, v.y), fmaxf(v.z, v.w)));
    }
#pragma unroll
    for (int o = 16; o; o >>= 1) m = fmaxf(m, __shfl_xor_sync(0xffffffffu, m, o));
    if ((tid & 31) == 0) red[tid >> 5] = m;
    __syncthreads();
    float mm = red[0];
#pragma unroll
    for (int i = 1; i < 8; i++) mm = fmaxf(mm, red[i]);
    __syncthreads();

    float sum = 0.f;
    for (int i = tid; i < kN / 4; i += 256) {
        float4 v = s4[i];
        sum += __expf(v.x - mm) + __expf(v.y - mm) + __expf(v.z - mm) + __expf(v.w - mm);
    }
#pragma unroll
    for (int o = 16; o; o >>= 1) sum += __shfl_xor_sync(0xffffffffu, sum, o);
    if ((tid & 31) == 0) red[tid >> 5] = sum;
    __syncthreads();
    if (tid == 0) {
        float tot = red[0];
        for (int i = 1; i < 8; i++) tot += red[i];
        g_lse[row] = mm + logf(tot);
    }
}

// ---------------- 6) logit = max_q (s - lse) ----------------
__global__ void __launch_bounds__(256) logit_kernel()
{
    __shared__ float ls[kNQ];
    const int tid = threadIdx.x;
    const int b = blockIdx.y;
    if (tid < kNQ) ls[tid] = g_lse[b * kNQ + tid];
    __syncthreads();
    const int n = blockIdx.x * 256 + tid;
    const float* s = g_S + (size_t)b * kNQ * kN + n;
    float best = -3.402823466e38f;
#pragma unroll 8
    for (int q = 0; q < kNQ; q++)
        best = fmaxf(best, s[(size_t)q * kN] - ls[q]);
    g_logit[b * kN + n] = best;
}

// ---------------- 7) top-1024 radix select + tie-aware compaction ----------------
__global__ void __launch_bounds__(1024) topk_kernel()
{
    const int b = blockIdx.x;
    const int tid = threadIdx.x;
    __shared__ unsigned su[kN];
    __shared__ int hist[256];
    __shared__ int sc[256];
    __shared__ int s_need, s_digit;
    __shared__ int wsum[32];
    const float* lg = g_logit + b * kN;

    for (int i = tid; i < kN; i += 1024) {
        unsigned x = __float_as_uint(lg[i]);
        su[i] = (x & 0x80000000u) ? ~x : (x ^ 0x80000000u);
    }
    if (tid == 0) s_need = kTOPK;

    unsigned prefix = 0, pmask = 0;
    for (int pass = 0; pass < 4; pass++) {
        const int shift = 24 - 8 * pass;
        if (tid < 256) hist[tid] = 0;
        __syncthreads();
        const int need = s_need;
        for (int i = tid; i < kN; i += 1024) {
            unsigned u = su[i];
            if ((u & pmask) == prefix) atomicAdd(&hist[(u >> shift) & 255], 1);
        }
        __syncthreads();
        if (tid < 256) sc[tid] = hist[255 - tid];
        __syncthreads();
        for (int off = 1; off < 256; off <<= 1) {
            int v = 0;
            if (tid < 256 && tid >= off) v = sc[tid - off];
            __syncthreads();
            if (tid < 256) sc[tid] += v;
            __syncthreads();
        }
        if (tid < 256) {
            int incl = sc[tid];
            int excl = (tid == 0) ? 0 : sc[tid - 1];
            if (incl >= need && excl < need) {
                s_digit = 255 - tid;
                s_need = need - excl;
            }
        }
        __syncthreads();
        prefix |= ((unsigned)s_digit) << shift;
        pmask |= 0xFFu << shift;
        __syncthreads();
    }
    const unsigned ut = prefix;
    const float thr = __uint_as_float((ut & 0x80000000u) ? (ut ^ 0x80000000u) : ~ut);

    float v[4];
    int gt = 0, eq = 0;
#pragma unroll
    for (int u = 0; u < 4; u++) {
        v[u] = lg[tid * 4 + u];
        gt += (v[u] > thr);
        eq += (v[u] == thr);
    }
    int x = (gt << 16) | eq;
    const int lane = tid & 31, wid = tid >> 5;
#pragma unroll
    for (int o = 1; o < 32; o <<= 1) {
        int y = __shfl_up_sync(0xffffffffu, x, o);
        if (lane >= o) x += y;
    }
    if (lane == 31) wsum[wid] = x;
    __syncthreads();
    if (wid == 0) {
        int y = wsum[lane];
#pragma unroll
        for (int o = 1; o < 32; o <<= 1) {
            int z = __shfl_up_sync(0xffffffffu, y, o);
            if (lane >= o) y += z;
        }
        wsum[lane] = y;
    }
    __syncthreads();
    const int warpbase = (wid == 0) ? 0 : wsum[wid - 1];
    const int incl = warpbase + x;
    int gt_before = (incl >> 16) - gt;
    int eq_before = (incl & 0xffff) - eq;
    const int total_gt = wsum[31] >> 16;
    const int need_eq = kTOPK - total_gt;
    int* outi = g_idx + b * kTOPK;
#pragma unroll
    for (int u = 0; u < 4; u++) {
        const int n = tid * 4 + u;
        if (v[u] > thr) {
            int pos = gt_before + min(eq_before, need_eq);
            outi[pos] = n;
            gt_before++;
        } else if (v[u] == thr) {
            if (eq_before < need_eq) outi[gt_before + eq_before] = n;
            eq_before++;
        }
    }
}

// ---------------- 8) gather ----------------
__global__ void __launch_bounds__(256) gather_kernel(const float* __restrict__ tf,
                                                     float* __restrict__ out)
{
    const int b = blockIdx.y, k = blockIdx.x;
    const int row = g_idx[b * kTOPK + k];
    const float4* src = (const float4*)(tf + ((size_t)b * kN + row) * kD);
    float4* dst = (float4*)(out + ((size_t)b * kTOPK + k) * kD);
    dst[threadIdx.x] = src[threadIdx.x];
}

// ---------------- launch ----------------
extern "C" void kernel_launch(void* const* d_in, const int* in_sizes, int n_in,
                              void* d_out, int out_size)
{
    (void)in_sizes; (void)n_in; (void)out_size;
    const float* tf  = (const float*)d_in[0];
    const float* den = (const float*)d_in[1];
    const float* qe  = (const float*)d_in[2];
    const float* kw  = (const float*)d_in[3];
    const float* kb  = (const float*)d_in[4];
    const float* w1  = (const float*)d_in[5];
    const float* b1  = (const float*)d_in[6];
    const float* w2  = (const float*)d_in[7];
    const float* b2  = (const float*)d_in[8];
    float* out = (float*)d_out;

    cudaFuncSetAttribute(scores_mma, cudaFuncAttributeMaxDynamicSharedMemorySize, SMEM_MMA);

    qw_kernel<<<dim3(kD / 128, kSPLIT), 256>>>(kw, qe);
    qwred_kernel<<<64, 256>>>();
    qb_kernel<<<1, 64>>>(qe, kb);
    prepb_kernel<<<256, 256>>>();
    density_kernel<<<kB * kN / 64, 256>>>(den, w1, b1, w2, b2);
    scores_mma<<<dim3(kN / 128, kB), 256, SMEM_MMA>>>(tf);
    lse_kernel<<<kB * kNQ, 256>>>();
    logit_kernel<<<dim3(kN / 256, kB), 256>>>();
    topk_kernel<<<kB, 1024>>>();
    gather_kernel<<<dim3(kTOPK, kB), 256>>>(tf, out);
}

// round 9
// speedup vs baseline: 1.1110x; 1.1110x over previous
#include <cuda_runtime.h>
#include <cstdint>

constexpr int kB = 8, kN = 4096, kD = 1024, kNQ = 64;
constexpr int kTOPK = 1024;
constexpr int KC = 16;     // K-chunk per smem stage
constexpr int AP = 132;    // smem pitch (floats)
constexpr int STG = KC * AP;
constexpr int kSPLIT = 16; // qw split-K

// ---------------- scratch (device globals; no allocations allowed) ----------------
__device__ float g_QW[kNQ * kD];            // (query_embed @ key_w^T) / 32
__device__ float g_QWp[kSPLIT * kNQ * kD];  // split-K partials
__device__ float g_qb[kNQ];                 // (query_embed @ key_b) / 32
__device__ float g_bias[kB * kN];           // density bias per token
__device__ float g_S[(size_t)kB * kNQ * kN];// scores [b][q][n]
__device__ float g_lse[kB * kNQ];           // logsumexp per (b,q)
__device__ float g_logit[kB * kN];          // max_q (s - lse) per token
__device__ int   g_idx[kB * kTOPK];         // selected indices, ascending

// ---------------- f32x2 packed-FP32 helpers (Blackwell FFMA2) ----------------
__device__ __forceinline__ void f32x2_unpack(unsigned long long v, float& lo, float& hi) {
    asm("mov.b64 {%0, %1}, %2;" : "=f"(lo), "=f"(hi) : "l"(v));
}
__device__ __forceinline__ unsigned long long f32x2_fma(unsigned long long a,
                                                        unsigned long long b,
                                                        unsigned long long c) {
    unsigned long long d;
    asm("fma.rn.f32x2 %0, %1, %2, %3;" : "=l"(d) : "l"(a), "l"(b), "l"(c));
    return d;
}

// ---------------- stage loaders for the 128x64 tile GEMM ----------------
// A tile: 128 rows x 16 k, stored TRANSPOSED As[k][row]  (row pairs -> f32x2 direct)
// B tile: 64 cols x 16 k, stored DUPLICATED Bs[k][2c..2c+1] = {B,B}
__device__ __forceinline__ void ldg_stage(const float* __restrict__ A,
                                          const float* __restrict__ Bm,
                                          int k0, float4 pa[2], float4& pb, int tid)
{
#pragma unroll
    for (int i = 0; i < 2; i++) {
        int idx = tid + i * 256;              // 512 float4 slots: r=idx>>2, c4=idx&3
        int r = idx >> 2, c4 = idx & 3;
        pa[i] = *(const float4*)(A + (size_t)r * kD + k0 + c4 * 4);
    }
    {
        int q = tid >> 2, c4 = tid & 3;       // 256 float4 slots
        pb = *(const float4*)(Bm + (size_t)q * kD + k0 + c4 * 4);
    }
}

__device__ __forceinline__ void sts_stage(float* As, float* Bs,
                                          const float4 pa[2], const float4& pb, int tid)
{
#pragma unroll
    for (int i = 0; i < 2; i++) {
        int idx = tid + i * 256;
        int r = idx >> 2, c4 = idx & 3;
        float* p = As + (c4 * 4) * AP + r;
        p[0] = pa[i].x; p[AP] = pa[i].y; p[2 * AP] = pa[i].z; p[3 * AP] = pa[i].w;
    }
    {
        int q = tid >> 2, c4 = tid & 3;
        float* p = Bs + (c4 * 4) * AP + 2 * q;
        p[0] = pb.x;          p[1] = pb.x;
        p[AP] = pb.y;         p[AP + 1] = pb.y;
        p[2 * AP] = pb.z;     p[2 * AP + 1] = pb.z;
        p[3 * AP] = pb.w;     p[3 * AP + 1] = pb.w;
    }
}

// C[r][c] = sum_{k in [kbeg,kend)} A[r][k] * Bm[c][k]; double-buffered.
// 256 threads: warp w -> cols 8w..8w+7; lane l -> rows 4l..4l+3 (as 2 f32x2 pairs).
__device__ __forceinline__ void gemm128x64(const float* __restrict__ A,
                                           const float* __restrict__ Bm,
                                           int kbeg, int kend,
                                           float* As, float* Bs,
                                           unsigned long long c2[2][8])
{
    const int tid = threadIdx.x;
    const int w = tid >> 5, l = tid & 31;
#pragma unroll
    for (int p = 0; p < 2; p++)
#pragma unroll
        for (int c = 0; c < 8; c++) c2[p][c] = 0ull;

    float4 pa[2]; float4 pb;
    ldg_stage(A, Bm, kbeg, pa, pb, tid);
    sts_stage(As, Bs, pa, pb, tid);
    __syncthreads();

    const int ns = (kend - kbeg) >> 4;
    for (int s = 0; s < ns; s++) {
        const float* Ac = As + (s & 1) * STG;
        const float* Bc = Bs + (s & 1) * STG;
        if (s + 1 < ns) ldg_stage(A, Bm, kbeg + (s + 1) * KC, pa, pb, tid);
#pragma unroll
        for (int k = 0; k < KC; k++) {
            ulonglong2 a = *(const ulonglong2*)(Ac + k * AP + 4 * l);
            const float* bp = Bc + k * AP + 16 * w;
            ulonglong2 b0 = *(const ulonglong2*)(bp);
            ulonglong2 b1 = *(const ulonglong2*)(bp + 4);
            ulonglong2 b2 = *(const ulonglong2*)(bp + 8);
            ulonglong2 b3 = *(const ulonglong2*)(bp + 12);
            c2[0][0] = f32x2_fma(a.x, b0.x, c2[0][0]);
            c2[0][1] = f32x2_fma(a.x, b0.y, c2[0][1]);
            c2[0][2] = f32x2_fma(a.x, b1.x, c2[0][2]);
            c2[0][3] = f32x2_fma(a.x, b1.y, c2[0][3]);
            c2[0][4] = f32x2_fma(a.x, b2.x, c2[0][4]);
            c2[0][5] = f32x2_fma(a.x, b2.y, c2[0][5]);
            c2[0][6] = f32x2_fma(a.x, b3.x, c2[0][6]);
            c2[0][7] = f32x2_fma(a.x, b3.y, c2[0][7]);
            c2[1][0] = f32x2_fma(a.y, b0.x, c2[1][0]);
            c2[1][1] = f32x2_fma(a.y, b0.y, c2[1][1]);
            c2[1][2] = f32x2_fma(a.y, b1.x, c2[1][2]);
            c2[1][3] = f32x2_fma(a.y, b1.y, c2[1][3]);
            c2[1][4] = f32x2_fma(a.y, b2.x, c2[1][4]);
            c2[1][5] = f32x2_fma(a.y, b2.y, c2[1][5]);
            c2[1][6] = f32x2_fma(a.y, b3.x, c2[1][6]);
            c2[1][7] = f32x2_fma(a.y, b3.y, c2[1][7]);
        }
        if (s + 1 < ns) {
            sts_stage(As + ((s + 1) & 1) * STG, Bs + ((s + 1) & 1) * STG, pa, pb, tid);
            __syncthreads();
        }
    }
}

// ---------------- 1) QW split-K partials ----------------
__global__ void __launch_bounds__(256, 2) qw_kernel(const float* __restrict__ kw,
                                                    const float* __restrict__ qe)
{
    __shared__ float As[2 * STG];
    __shared__ float Bs[2 * STG];
    const int d0 = blockIdx.x * 128;
    const int kc = blockIdx.y;
    unsigned long long c2[2][8];
    gemm128x64(kw + (size_t)d0 * kD, qe, kc * 64, kc * 64 + 64, As, Bs, c2);

    const int tid = threadIdx.x, w = tid >> 5, l = tid & 31;
    const int dbase = d0 + 4 * l;
    float* gp = g_QWp + (size_t)kc * (kNQ * kD);
#pragma unroll
    for (int c = 0; c < 8; c++) {
        const int q = 8 * w + c;
        float4 o;
        f32x2_unpack(c2[0][c], o.x, o.y);
        f32x2_unpack(c2[1][c], o.z, o.w);
        *(float4*)(gp + (size_t)q * kD + dbase) = o;
    }
}

// ---------------- 1b) reduce partials, scale 1/32 ----------------
__global__ void __launch_bounds__(256) qwred_kernel()
{
    const int i4 = blockIdx.x * 256 + threadIdx.x;
    float4 acc = make_float4(0.f, 0.f, 0.f, 0.f);
#pragma unroll
    for (int c = 0; c < kSPLIT; c++) {
        float4 v = ((const float4*)g_QWp)[(size_t)c * 16384 + i4];
        acc.x += v.x; acc.y += v.y; acc.z += v.z; acc.w += v.w;
    }
    acc.x *= 0.03125f; acc.y *= 0.03125f; acc.z *= 0.03125f; acc.w *= 0.03125f;
    ((float4*)g_QW)[i4] = acc;
}

// ---------------- 2) qb = (query_embed @ key_b)/32 ----------------
__global__ void qb_kernel(const float* __restrict__ qe, const float* __restrict__ kb)
{
    const int q = threadIdx.x;            // 64 threads
    const float* row = qe + (size_t)q * kD;
    float s0 = 0.f, s1 = 0.f, s2 = 0.f, s3 = 0.f;
    for (int h = 0; h < kD; h += 4) {
        s0 = fmaf(row[h + 0], kb[h + 0], s0);
        s1 = fmaf(row[h + 1], kb[h + 1], s1);
        s2 = fmaf(row[h + 2], kb[h + 2], s2);
        s3 = fmaf(row[h + 3], kb[h + 3], s3);
    }
    g_qb[q] = ((s0 + s1) + (s2 + s3)) * 0.03125f;
}

// ---------------- 3) density bias: 4 threads per token ----------------
__global__ void __launch_bounds__(256) density_kernel(
    const float* __restrict__ dens, const float* __restrict__ w1,
    const float* __restrict__ b1, const float* __restrict__ w2,
    const float* __restrict__ b2)
{
    __shared__ float4 sw1[512], sb1[512], sw2[512];
    const int tid = threadIdx.x;
    for (int i = tid; i < 512; i += 256) {
        sw1[i] = ((const float4*)w1)[i];
        sb1[i] = ((const float4*)b1)[i];
        sw2[i] = ((const float4*)w2)[i];
    }
    __syncthreads();
    const int t = blockIdx.x * 64 + (tid >> 2);
    const int sub = tid & 3;
    const float d = dens[t];
    float a0 = 0.f, a1 = 0.f, a2 = 0.f, a3 = 0.f;
    const int j0 = sub * 128;
#pragma unroll 4
    for (int j = j0; j < j0 + 128; j++) {
        float4 w = sw1[j], bb = sb1[j], v = sw2[j];
        float h0 = fmaxf(fmaf(d, w.x, bb.x), 0.f);
        float h1 = fmaxf(fmaf(d, w.y, bb.y), 0.f);
        float h2 = fmaxf(fmaf(d, w.z, bb.z), 0.f);
        float h3 = fmaxf(fmaf(d, w.w, bb.w), 0.f);
        a0 = fmaf(h0, v.x, a0);
        a1 = fmaf(h1, v.y, a1);
        a2 = fmaf(h2, v.z, a2);
        a3 = fmaf(h3, v.w, a3);
    }
    float v = (a0 + a1) + (a2 + a3);
    v += __shfl_xor_sync(0xffffffffu, v, 1);
    v += __shfl_xor_sync(0xffffffffu, v, 2);
    if (sub == 0) g_bias[t] = v + b2[0];
}

// ---------------- 4) scores S[b][q][n] = tf·QW^T + qb + bias ----------------
__global__ void __launch_bounds__(256, 3) scores_kernel(const float* __restrict__ tf)
{
    __shared__ float As[2 * STG];
    __shared__ float Bs[2 * STG];
    const int b = blockIdx.y;
    const int n0 = blockIdx.x * 128;
    unsigned long long c2[2][8];
    gemm128x64(tf + ((size_t)b * kN + n0) * kD, g_QW, 0, kD, As, Bs, c2);

    const int tid = threadIdx.x, w = tid >> 5, l = tid & 31;
    const int nbase = n0 + 4 * l;
    float bv[4];
#pragma unroll
    for (int j = 0; j < 4; j++) bv[j] = g_bias[b * kN + nbase + j];
#pragma unroll
    for (int c = 0; c < 8; c++) {
        const int q = 8 * w + c;
        const float add = g_qb[q];
        float4 o;
        f32x2_unpack(c2[0][c], o.x, o.y);
        f32x2_unpack(c2[1][c], o.z, o.w);
        o.x += add + bv[0];
        o.y += add + bv[1];
        o.z += add + bv[2];
        o.w += add + bv[3];
        *(float4*)(g_S + ((size_t)(b * kNQ + q)) * kN + nbase) = o;
    }
}

// ---------------- 5) per-(b,q) logsumexp over n ----------------
__global__ void __launch_bounds__(256) lse_kernel()
{
    const int row = blockIdx.x;           // 0..511
    const float4* s4 = (const float4*)(g_S + (size_t)row * kN);
    const int tid = threadIdx.x;
    __shared__ float red[8];

    float m = -3.402823466e38f;
    for (int i = tid; i < kN / 4; i += 256) {
        float4 v = s4[i];
        m = fmaxf(m, fmaxf(fmaxf(v.x, v.y), fmaxf(v.z, v.w)));
    }
#pragma unroll
    for (int o = 16; o; o >>= 1) m = fmaxf(m, __shfl_xor_sync(0xffffffffu, m, o));
    if ((tid & 31) == 0) red[tid >> 5] = m;
    __syncthreads();
    float mm = red[0];
#pragma unroll
    for (int i = 1; i < 8; i++) mm = fmaxf(mm, red[i]);
    __syncthreads();

    float sum = 0.f;
    for (int i = tid; i < kN / 4; i += 256) {
        float4 v = s4[i];
        sum += __expf(v.x - mm) + __expf(v.y - mm) + __expf(v.z - mm) + __expf(v.w - mm);
    }
#pragma unroll
    for (int o = 16; o; o >>= 1) sum += __shfl_xor_sync(0xffffffffu, sum, o);
    if ((tid & 31) == 0) red[tid >> 5] = sum;
    __syncthreads();
    if (tid == 0) {
        float tot = red[0];
        for (int i = 1; i < 8; i++) tot += red[i];
        g_lse[row] = mm + logf(tot);
    }
}

// ---------------- 6) importance logit = max_q (s - lse) ----------------
__global__ void __launch_bounds__(256) logit_kernel()
{
    __shared__ float ls[kNQ];
    const int tid = threadIdx.x;
    const int b = blockIdx.y;
    if (tid < kNQ) ls[tid] = g_lse[b * kNQ + tid];
    __syncthreads();
    const int n = blockIdx.x * 256 + tid;
    const float* s = g_S + (size_t)b * kNQ * kN + n;
    float best = -3.402823466e38f;
#pragma unroll 8
    for (int q = 0; q < kNQ; q++)
        best = fmaxf(best, s[(size_t)q * kN] - ls[q]);
    g_logit[b * kN + n] = best;
}

// ---------------- 7) top-1024 radix select + tie-aware compaction ----------------
__global__ void __launch_bounds__(1024) topk_kernel()
{
    const int b = blockIdx.x;
    const int tid = threadIdx.x;
    __shared__ unsigned su[kN];
    __shared__ int hist[256];
    __shared__ int sc[256];
    __shared__ int s_need, s_digit;
    __shared__ int wsum[32];
    const float* lg = g_logit + b * kN;

    for (int i = tid; i < kN; i += 1024) {
        unsigned x = __float_as_uint(lg[i]);
        su[i] = (x & 0x80000000u) ? ~x : (x ^ 0x80000000u);
    }
    if (tid == 0) s_need = kTOPK;

    unsigned prefix = 0, pmask = 0;
    for (int pass = 0; pass < 4; pass++) {
        const int shift = 24 - 8 * pass;
        if (tid < 256) hist[tid] = 0;
        __syncthreads();
        const int need = s_need;
        for (int i = tid; i < kN; i += 1024) {
            unsigned u = su[i];
            if ((u & pmask) == prefix) atomicAdd(&hist[(u >> shift) & 255], 1);
        }
        __syncthreads();
        if (tid < 256) sc[tid] = hist[255 - tid];
        __syncthreads();
        for (int off = 1; off < 256; off <<= 1) {
            int v = 0;
            if (tid < 256 && tid >= off) v = sc[tid - off];
            __syncthreads();
            if (tid < 256) sc[tid] += v;
            __syncthreads();
        }
        if (tid < 256) {
            int incl = sc[tid];
            int excl = (tid == 0) ? 0 : sc[tid - 1];
            if (incl >= need && excl < need) {
                s_digit = 255 - tid;
                s_need = need - excl;
            }
        }
        __syncthreads();
        prefix |= ((unsigned)s_digit) << shift;
        pmask |= 0xFFu << shift;
        __syncthreads();
    }
    const unsigned ut = prefix;
    const float thr = __uint_as_float((ut & 0x80000000u) ? (ut ^ 0x80000000u) : ~ut);

    float v[4];
    int gt = 0, eq = 0;
#pragma unroll
    for (int u = 0; u < 4; u++) {
        v[u] = lg[tid * 4 + u];
        gt += (v[u] > thr);
        eq += (v[u] == thr);
    }
    int x = (gt << 16) | eq;
    const int lane = tid & 31, wid = tid >> 5;
#pragma unroll
    for (int o = 1; o < 32; o <<= 1) {
        int y = __shfl_up_sync(0xffffffffu, x, o);
        if (lane >= o) x += y;
    }
    if (lane == 31) wsum[wid] = x;
    __syncthreads();
    if (wid == 0) {
        int y = wsum[lane];
#pragma unroll
        for (int o = 1; o < 32; o <<= 1) {
            int z = __shfl_up_sync(0xffffffffu, y, o);
            if (lane >= o) y += z;
        }
        wsum[lane] = y;
    }
    __syncthreads();
    const int warpbase = (wid == 0) ? 0 : wsum[wid - 1];
    const int incl = warpbase + x;
    int gt_before = (incl >> 16) - gt;
    int eq_before = (incl & 0xffff) - eq;
    const int total_gt = wsum[31] >> 16;
    const int need_eq = kTOPK - total_gt;
    int* outi = g_idx + b * kTOPK;
#pragma unroll
    for (int u = 0; u < 4; u++) {
        const int n = tid * 4 + u;
        if (v[u] > thr) {
            int pos = gt_before + min(eq_before, need_eq);
            outi[pos] = n;
            gt_before++;
        } else if (v[u] == thr) {
            if (eq_before < need_eq) outi[gt_before + eq_before] = n;
            eq_before++;
        }
    }
}

// ---------------- 8) gather selected rows ----------------
__global__ void __launch_bounds__(256) gather_kernel(const float* __restrict__ tf,
                                                     float* __restrict__ out)
{
    const int b = blockIdx.y, k = blockIdx.x;
    const int row = g_idx[b * kTOPK + k];
    const float4* src = (const float4*)(tf + ((size_t)b * kN + row) * kD);
    float4* dst = (float4*)(out + ((size_t)b * kTOPK + k) * kD);
    dst[threadIdx.x] = src[threadIdx.x];
}

// ---------------- launch ----------------
extern "C" void kernel_launch(void* const* d_in, const int* in_sizes, int n_in,
                              void* d_out, int out_size)
{
    (void)in_sizes; (void)n_in; (void)out_size;
    const float* tf  = (const float*)d_in[0];   // token_features  [8,4096,1024]
    const float* den = (const float*)d_in[1];   // token_densities [8,4096]
    const float* qe  = (const float*)d_in[2];   // query_embed     [64,1024]
    const float* kw  = (const float*)d_in[3];   // key_w           [1024,1024]
    const float* kb  = (const float*)d_in[4];   // key_b           [1024]
    const float* w1  = (const float*)d_in[5];   // de_w1           [1,2048]
    const float* b1  = (const float*)d_in[6];   // de_b1           [2048]
    const float* w2  = (const float*)d_in[7];   // de_w2           [2048,1]
    const float* b2  = (const float*)d_in[8];   // de_b2           [1]
    float* out = (float*)d_out;                 // [8,1024,1024] f32

    qw_kernel<<<dim3(kD / 128, kSPLIT), 256>>>(kw, qe);
    qwred_kernel<<<64, 256>>>();
    qb_kernel<<<1, 64>>>(qe, kb);
    density_kernel<<<kB * kN / 64, 256>>>(den, w1, b1, w2, b2);
    scores_kernel<<<dim3(kN / 128, kB), 256>>>(tf);
    lse_kernel<<<kB * kNQ, 256>>>();
    logit_kernel<<<dim3(kN / 256, kB), 256>>>();
    topk_kernel<<<kB, 1024>>>();
    gather_kernel<<<dim3(kTOPK, kB), 256>>>(tf, out);
}

// round 10
// speedup vs baseline: 1.5965x; 1.4370x over previous
#include <cuda_runtime.h>
#include <cstdint>

constexpr int kB = 8, kN = 4096, kD = 1024, kNQ = 64;
constexpr int kTOPK = 1024, kTWOH = 2048;
constexpr int KC = 16;     // K-chunk per smem stage
constexpr int AP = 132;    // smem pitch (floats)
constexpr int STG = KC * AP;
constexpr int kSPLIT = 16; // qw split-K

// ---------------- scratch (device globals; no allocations allowed) ----------------
__device__ float g_QW[kNQ * kD];            // (query_embed @ key_w^T) / 32
__device__ float g_QWp[kSPLIT * kNQ * kD];  // split-K partials
__device__ float g_qb[kNQ];                 // (query_embed @ key_b) / 32
__device__ float g_bias[kB * kN];           // density bias per token
__device__ float g_S[(size_t)kB * kNQ * kN];// scores [b][q][n]
__device__ float g_lse[kB * kNQ];           // logsumexp per (b,q)
__device__ float g_logit[kB * kN];          // max_q (s - lse) per token
__device__ int   g_idx[kB * kTOPK];         // selected indices, ascending

// ---------------- f32x2 packed-FP32 helpers (Blackwell FFMA2) ----------------
__device__ __forceinline__ void f32x2_unpack(unsigned long long v, float& lo, float& hi) {
    asm("mov.b64 {%0, %1}, %2;" : "=f"(lo), "=f"(hi) : "l"(v));
}
__device__ __forceinline__ unsigned long long f32x2_fma(unsigned long long a,
                                                        unsigned long long b,
                                                        unsigned long long c) {
    unsigned long long d;
    asm("fma.rn.f32x2 %0, %1, %2, %3;" : "=l"(d) : "l"(a), "l"(b), "l"(c));
    return d;
}

// ---------------- stage loaders for the 128x64 tile GEMM ----------------
// A tile: 128 rows x 16 k, stored TRANSPOSED As[k][row]  (row pairs -> f32x2 direct)
// B tile: 64 cols x 16 k, stored DUPLICATED Bs[k][2c..2c+1] = {B,B}
__device__ __forceinline__ void ldg_stage(const float* __restrict__ A,
                                          const float* __restrict__ Bm,
                                          int k0, float4 pa[2], float4& pb, int tid)
{
#pragma unroll
    for (int i = 0; i < 2; i++) {
        int idx = tid + i * 256;              // 512 float4 slots: r=idx>>2, c4=idx&3
        int r = idx >> 2, c4 = idx & 3;
        pa[i] = *(const float4*)(A + (size_t)r * kD + k0 + c4 * 4);
    }
    {
        int q = tid >> 2, c4 = tid & 3;       // 256 float4 slots
        pb = *(const float4*)(Bm + (size_t)q * kD + k0 + c4 * 4);
    }
}

__device__ __forceinline__ void sts_stage(float* As, float* Bs,
                                          const float4 pa[2], const float4& pb, int tid)
{
#pragma unroll
    for (int i = 0; i < 2; i++) {
        int idx = tid + i * 256;
        int r = idx >> 2, c4 = idx & 3;
        float* p = As + (c4 * 4) * AP + r;
        p[0] = pa[i].x; p[AP] = pa[i].y; p[2 * AP] = pa[i].z; p[3 * AP] = pa[i].w;
    }
    {
        int q = tid >> 2, c4 = tid & 3;
        float* p = Bs + (c4 * 4) * AP + 2 * q;
        p[0] = pb.x;          p[1] = pb.x;
        p[AP] = pb.y;         p[AP + 1] = pb.y;
        p[2 * AP] = pb.z;     p[2 * AP + 1] = pb.z;
        p[3 * AP] = pb.w;     p[3 * AP + 1] = pb.w;
    }
}

// C[r][c] = sum_{k in [kbeg,kend)} A[r][k] * Bm[c][k]; double-buffered.
// 256 threads: warp w -> cols 8w..8w+7; lane l -> rows 4l..4l+3 (as 2 f32x2 pairs).
__device__ __forceinline__ void gemm128x64(const float* __restrict__ A,
                                           const float* __restrict__ Bm,
                                           int kbeg, int kend,
                                           float* As, float* Bs,
                                           unsigned long long c2[2][8])
{
    const int tid = threadIdx.x;
    const int w = tid >> 5, l = tid & 31;
#pragma unroll
    for (int p = 0; p < 2; p++)
#pragma unroll
        for (int c = 0; c < 8; c++) c2[p][c] = 0ull;

    float4 pa[2]; float4 pb;
    ldg_stage(A, Bm, kbeg, pa, pb, tid);
    sts_stage(As, Bs, pa, pb, tid);
    __syncthreads();

    const int ns = (kend - kbeg) >> 4;
    for (int s = 0; s < ns; s++) {
        const float* Ac = As + (s & 1) * STG;
        const float* Bc = Bs + (s & 1) * STG;
        if (s + 1 < ns) ldg_stage(A, Bm, kbeg + (s + 1) * KC, pa, pb, tid);
#pragma unroll
        for (int k = 0; k < KC; k++) {
            ulonglong2 a = *(const ulonglong2*)(Ac + k * AP + 4 * l);
            const float* bp = Bc + k * AP + 16 * w;
            ulonglong2 b0 = *(const ulonglong2*)(bp);
            ulonglong2 b1 = *(const ulonglong2*)(bp + 4);
            ulonglong2 b2 = *(const ulonglong2*)(bp + 8);
            ulonglong2 b3 = *(const ulonglong2*)(bp + 12);
            c2[0][0] = f32x2_fma(a.x, b0.x, c2[0][0]);
            c2[0][1] = f32x2_fma(a.x, b0.y, c2[0][1]);
            c2[0][2] = f32x2_fma(a.x, b1.x, c2[0][2]);
            c2[0][3] = f32x2_fma(a.x, b1.y, c2[0][3]);
            c2[0][4] = f32x2_fma(a.x, b2.x, c2[0][4]);
            c2[0][5] = f32x2_fma(a.x, b2.y, c2[0][5]);
            c2[0][6] = f32x2_fma(a.x, b3.x, c2[0][6]);
            c2[0][7] = f32x2_fma(a.x, b3.y, c2[0][7]);
            c2[1][0] = f32x2_fma(a.y, b0.x, c2[1][0]);
            c2[1][1] = f32x2_fma(a.y, b0.y, c2[1][1]);
            c2[1][2] = f32x2_fma(a.y, b1.x, c2[1][2]);
            c2[1][3] = f32x2_fma(a.y, b1.y, c2[1][3]);
            c2[1][4] = f32x2_fma(a.y, b2.x, c2[1][4]);
            c2[1][5] = f32x2_fma(a.y, b2.y, c2[1][5]);
            c2[1][6] = f32x2_fma(a.y, b3.x, c2[1][6]);
            c2[1][7] = f32x2_fma(a.y, b3.y, c2[1][7]);
        }
        if (s + 1 < ns) {
            sts_stage(As + ((s + 1) & 1) * STG, Bs + ((s + 1) & 1) * STG, pa, pb, tid);
            __syncthreads();
        }
    }
}

// ---------------- 1) QW split-K partials ----------------
__global__ void __launch_bounds__(256, 2) qw_kernel(const float* __restrict__ kw,
                                                    const float* __restrict__ qe)
{
    __shared__ float As[2 * STG];
    __shared__ float Bs[2 * STG];
    const int d0 = blockIdx.x * 128;
    const int kc = blockIdx.y;
    unsigned long long c2[2][8];
    gemm128x64(kw + (size_t)d0 * kD, qe, kc * 64, kc * 64 + 64, As, Bs, c2);

    const int tid = threadIdx.x, w = tid >> 5, l = tid & 31;
    const int dbase = d0 + 4 * l;
    float* gp = g_QWp + (size_t)kc * (kNQ * kD);
#pragma unroll
    for (int c = 0; c < 8; c++) {
        const int q = 8 * w + c;
        float4 o;
        f32x2_unpack(c2[0][c], o.x, o.y);
        f32x2_unpack(c2[1][c], o.z, o.w);
        *(float4*)(gp + (size_t)q * kD + dbase) = o;
    }
}

// ---------------- 1b) reduce partials, scale 1/32 ----------------
__global__ void __launch_bounds__(256) qwred_kernel()
{
    const int i4 = blockIdx.x * 256 + threadIdx.x;
    float4 acc = make_float4(0.f, 0.f, 0.f, 0.f);
#pragma unroll
    for (int c = 0; c < kSPLIT; c++) {
        float4 v = ((const float4*)g_QWp)[(size_t)c * 16384 + i4];
        acc.x += v.x; acc.y += v.y; acc.z += v.z; acc.w += v.w;
    }
    acc.x *= 0.03125f; acc.y *= 0.03125f; acc.z *= 0.03125f; acc.w *= 0.03125f;
    ((float4*)g_QW)[i4] = acc;
}

// ---------------- 2) qb = (query_embed @ key_b)/32 ----------------
__global__ void qb_kernel(const float* __restrict__ qe, const float* __restrict__ kb)
{
    const int q = threadIdx.x;            // 64 threads
    const float* row = qe + (size_t)q * kD;
    float s0 = 0.f, s1 = 0.f, s2 = 0.f, s3 = 0.f;
    for (int h = 0; h < kD; h += 4) {
        s0 = fmaf(row[h + 0], kb[h + 0], s0);
        s1 = fmaf(row[h + 1], kb[h + 1], s1);
        s2 = fmaf(row[h + 2], kb[h + 2], s2);
        s3 = fmaf(row[h + 3], kb[h + 3], s3);
    }
    g_qb[q] = ((s0 + s1) + (s2 + s3)) * 0.03125f;
}

// ---------------- 3) density bias (1 thread/token, broadcast smem) ----------------
__global__ void __launch_bounds__(256) density_kernel(
    const float* __restrict__ dens, const float* __restrict__ w1,
    const float* __restrict__ b1, const float* __restrict__ w2,
    const float* __restrict__ b2)
{
    __shared__ float4 sw1[512], sb1[512], sw2[512];
    const int tid = threadIdx.x;
    for (int i = tid; i < 512; i += 256) {
        sw1[i] = ((const float4*)w1)[i];
        sb1[i] = ((const float4*)b1)[i];
        sw2[i] = ((const float4*)w2)[i];
    }
    __syncthreads();
    const int t = blockIdx.x * 256 + tid;
    const float d = dens[t];
    float a0 = 0.f, a1 = 0.f, a2 = 0.f, a3 = 0.f;
#pragma unroll 4
    for (int j = 0; j < 512; j++) {
        float4 w = sw1[j], bb = sb1[j], v = sw2[j];
        float h0 = fmaxf(fmaf(d, w.x, bb.x), 0.f);
        float h1 = fmaxf(fmaf(d, w.y, bb.y), 0.f);
        float h2 = fmaxf(fmaf(d, w.z, bb.z), 0.f);
        float h3 = fmaxf(fmaf(d, w.w, bb.w), 0.f);
        a0 = fmaf(h0, v.x, a0);
        a1 = fmaf(h1, v.y, a1);
        a2 = fmaf(h2, v.z, a2);
        a3 = fmaf(h3, v.w, a3);
    }
    g_bias[t] = (a0 + a1) + (a2 + a3) + b2[0];
}

// ---------------- 4) scores S[b][q][n] = tf·QW^T + qb + bias ----------------
__global__ void __launch_bounds__(256, 2) scores_kernel(const float* __restrict__ tf)
{
    __shared__ float As[2 * STG];
    __shared__ float Bs[2 * STG];
    const int b = blockIdx.y;
    const int n0 = blockIdx.x * 128;
    unsigned long long c2[2][8];
    gemm128x64(tf + ((size_t)b * kN + n0) * kD, g_QW, 0, kD, As, Bs, c2);

    const int tid = threadIdx.x, w = tid >> 5, l = tid & 31;
    const int nbase = n0 + 4 * l;
    float bv[4];
#pragma unroll
    for (int j = 0; j < 4; j++) bv[j] = g_bias[b * kN + nbase + j];
#pragma unroll
    for (int c = 0; c < 8; c++) {
        const int q = 8 * w + c;
        const float add = g_qb[q];
        float4 o;
        f32x2_unpack(c2[0][c], o.x, o.y);
        f32x2_unpack(c2[1][c], o.z, o.w);
        o.x += add + bv[0];
        o.y += add + bv[1];
        o.z += add + bv[2];
        o.w += add + bv[3];
        *(float4*)(g_S + ((size_t)(b * kNQ + q)) * kN + nbase) = o;
    }
}

// ---------------- 5) per-(b,q) logsumexp over n ----------------
__global__ void __launch_bounds__(256) lse_kernel()
{
    const int row = blockIdx.x;           // 0..511
    const float4* s4 = (const float4*)(g_S + (size_t)row * kN);
    const int tid = threadIdx.x;
    __shared__ float red[8];

    float m = -3.402823466e38f;
    for (int i = tid; i < kN / 4; i += 256) {
        float4 v = s4[i];
        m = fmaxf(m, fmaxf(fmaxf(v.x, v.y), fmaxf(v.z, v.w)));
    }
#pragma unroll
    for (int o = 16; o; o >>= 1) m = fmaxf(m, __shfl_xor_sync(0xffffffffu, m, o));
    if ((tid & 31) == 0) red[tid >> 5] = m;
    __syncthreads();
    float mm = red[0];
#pragma unroll
    for (int i = 1; i < 8; i++) mm = fmaxf(mm, red[i]);
    __syncthreads();

    float sum = 0.f;
    for (int i = tid; i < kN / 4; i += 256) {
        float4 v = s4[i];
        sum += __expf(v.x - mm) + __expf(v.y - mm) + __expf(v.z - mm) + __expf(v.w - mm);
    }
#pragma unroll
    for (int o = 16; o; o >>= 1) sum += __shfl_xor_sync(0xffffffffu, sum, o);
    if ((tid & 31) == 0) red[tid >> 5] = sum;
    __syncthreads();
    if (tid == 0) {
        float tot = red[0];
        for (int i = 1; i < 8; i++) tot += red[i];
        g_lse[row] = mm + logf(tot);
    }
}

// ---------------- 6) importance logit = max_q (s - lse) ----------------
__global__ void __launch_bounds__(256) logit_kernel()
{
    __shared__ float ls[kNQ];
    const int tid = threadIdx.x;
    const int b = blockIdx.y;
    if (tid < kNQ) ls[tid] = g_lse[b * kNQ + tid];
    __syncthreads();
    const int n = blockIdx.x * 256 + tid;
    const float* s = g_S + (size_t)b * kNQ * kN + n;
    float best = -3.402823466e38f;
#pragma unroll 8
    for (int q = 0; q < kNQ; q++)
        best = fmaxf(best, s[(size_t)q * kN] - ls[q]);
    g_logit[b * kN + n] = best;
}

// ---------------- 7) top-1024 radix select + tie-aware compaction ----------------
__global__ void __launch_bounds__(1024) topk_kernel()
{
    const int b = blockIdx.x;
    const int tid = threadIdx.x;
    __shared__ unsigned su[kN];
    __shared__ int hist[256];
    __shared__ int sc[256];
    __shared__ int s_need, s_digit;
    __shared__ int wsum[32];
    const float* lg = g_logit + b * kN;

    for (int i = tid; i < kN; i += 1024) {
        unsigned x = __float_as_uint(lg[i]);
        su[i] = (x & 0x80000000u) ? ~x : (x ^ 0x80000000u);
    }
    if (tid == 0) s_need = kTOPK;

    unsigned prefix = 0, pmask = 0;
    for (int pass = 0; pass < 4; pass++) {
        const int shift = 24 - 8 * pass;
        if (tid < 256) hist[tid] = 0;
        __syncthreads();
        const int need = s_need;
        for (int i = tid; i < kN; i += 1024) {
            unsigned u = su[i];
            if ((u & pmask) == prefix) atomicAdd(&hist[(u >> shift) & 255], 1);
        }
        __syncthreads();
        if (tid < 256) sc[tid] = hist[255 - tid];
        __syncthreads();
        for (int off = 1; off < 256; off <<= 1) {
            int v = 0;
            if (tid < 256 && tid >= off) v = sc[tid - off];
            __syncthreads();
            if (tid < 256) sc[tid] += v;
            __syncthreads();
        }
        if (tid < 256) {
            int incl = sc[tid];
            int excl = (tid == 0) ? 0 : sc[tid - 1];
            if (incl >= need && excl < need) {
                s_digit = 255 - tid;
                s_need = need - excl;
            }
        }
        __syncthreads();
        prefix |= ((unsigned)s_digit) << shift;
        pmask |= 0xFFu << shift;
        __syncthreads();
    }
    const unsigned ut = prefix;
    const float thr = __uint_as_float((ut & 0x80000000u) ? (ut ^ 0x80000000u) : ~ut);

    float v[4];
    int gt = 0, eq = 0;
#pragma unroll
    for (int u = 0; u < 4; u++) {
        v[u] = lg[tid * 4 + u];
        gt += (v[u] > thr);
        eq += (v[u] == thr);
    }
    int x = (gt << 16) | eq;
    const int lane = tid & 31, wid = tid >> 5;
#pragma unroll
    for (int o = 1; o < 32; o <<= 1) {
        int y = __shfl_up_sync(0xffffffffu, x, o);
        if (lane >= o) x += y;
    }
    if (lane == 31) wsum[wid] = x;
    __syncthreads();
    if (wid == 0) {
        int y = wsum[lane];
#pragma unroll
        for (int o = 1; o < 32; o <<= 1) {
            int z = __shfl_up_sync(0xffffffffu, y, o);
            if (lane >= o) y += z;
        }
        wsum[lane] = y;
    }
    __syncthreads();
    const int warpbase = (wid == 0) ? 0 : wsum[wid - 1];
    const int incl = warpbase + x;
    int gt_before = (incl >> 16) - gt;
    int eq_before = (incl & 0xffff) - eq;
    const int total_gt = wsum[31] >> 16;
    const int need_eq = kTOPK - total_gt;
    int* outi = g_idx + b * kTOPK;
#pragma unroll
    for (int u = 0; u < 4; u++) {
        const int n = tid * 4 + u;
        if (v[u] > thr) {
            int pos = gt_before + min(eq_before, need_eq);
            outi[pos] = n;
            gt_before++;
        } else if (v[u] == thr) {
            if (eq_before < need_eq) outi[gt_before + eq_before] = n;
            eq_before++;
        }
    }
}

// ---------------- 8) gather selected rows ----------------
__global__ void __launch_bounds__(256) gather_kernel(const float* __restrict__ tf,
                                                     float* __restrict__ out)
{
    const int b = blockIdx.y, k = blockIdx.x;
    const int row = g_idx[b * kTOPK + k];
    const float4* src = (const float4*)(tf + ((size_t)b * kN + row) * kD);
    float4* dst = (float4*)(out + ((size_t)b * kTOPK + k) * kD);
    dst[threadIdx.x] = src[threadIdx.x];
}

// ---------------- launch ----------------
extern "C" void kernel_launch(void* const* d_in, const int* in_sizes, int n_in,
                              void* d_out, int out_size)
{
    (void)in_sizes; (void)n_in; (void)out_size;
    const float* tf  = (const float*)d_in[0];   // token_features  [8,4096,1024]
    const float* den = (const float*)d_in[1];   // token_densities [8,4096]
    const float* qe  = (const float*)d_in[2];   // query_embed     [64,1024]
    const float* kw  = (const float*)d_in[3];   // key_w           [1024,1024]
    const float* kb  = (const float*)d_in[4];   // key_b           [1024]
    const float* w1  = (const float*)d_in[5];   // de_w1           [1,2048]
    const float* b1  = (const float*)d_in[6];   // de_b1           [2048]
    const float* w2  = (const float*)d_in[7];   // de_w2           [2048,1]
    const float* b2  = (const float*)d_in[8];   // de_b2           [1]
    float* out = (float*)d_out;                 // [8,1024,1024] f32

    qw_kernel<<<dim3(kD / 128, kSPLIT), 256>>>(kw, qe);
    qwred_kernel<<<64, 256>>>();
    qb_kernel<<<1, 64>>>(qe, kb);
    density_kernel<<<kB * kN / 256, 256>>>(den, w1, b1, w2, b2);
    scores_kernel<<<dim3(kN / 128, kB), 256>>>(tf);
    lse_kernel<<<kB * kNQ, 256>>>();
    logit_kernel<<<dim3(kN / 256, kB), 256>>>();
    topk_kernel<<<kB, 1024>>>();
    gather_kernel<<<dim3(kTOPK, kB), 256>>>(tf, out);
}